// round 16
// baseline (speedup 1.0000x reference)
#include <cuda_runtime.h>
#include <cuda_fp16.h>
#include <cstdint>

// Problem constants
#define BB 4
#define SS 2048
#define DD 1024
#define HH 16
#define DHH 64
#define MTOT (BB*SS)     // 8192
#define NTOT (3*DD)      // 3072
#define KTOT (DD)        // 1024

#define QKVN ((size_t)BB*HH*SS*DHH)

// Q pre-scale: 1/sqrt(64) * log2(e)  (softmax done in exp2 space)
#define QSCALE 0.1803368801111204f

// Scratch: fp16 single-precision-pass operands
__device__ __align__(16) __half g_A[(size_t)MTOT*KTOT];   // x   [M, K] K-major
__device__ __align__(16) __half g_B[(size_t)NTOT*KTOT];   // W^T [N, K] K-major
__device__ __align__(16) __half g_Qh[QKVN];               // [B,H,S,64] (pre-scaled)
__device__ __align__(16) __half g_Kh[QKVN];               // [B,H,S,64]
__device__ __align__(16) __half g_Vh[QKVN];               // [B,H,64,S] (transposed)

// ---------------------------------------------------------------------------
// Helpers (sm_103 baseline-safe: ldmatrix / mma.sync / cp.async only)
// ---------------------------------------------------------------------------
__device__ __forceinline__ uint32_t smem_u32(const void* p) {
    uint32_t a;
    asm("{ .reg .u64 t; cvta.to.shared.u64 t, %1; cvt.u32.u64 %0, t; }" : "=r"(a) : "l"(p));
    return a;
}
__device__ __forceinline__ void ldm_x4(uint32_t* r, uint32_t addr) {
    asm volatile("ldmatrix.sync.aligned.m8n8.x4.shared.b16 {%0,%1,%2,%3}, [%4];"
        : "=r"(r[0]), "=r"(r[1]), "=r"(r[2]), "=r"(r[3]) : "r"(addr));
}
__device__ __forceinline__ void mma16816(float* d, const uint32_t* a, uint32_t b0, uint32_t b1) {
    asm volatile("mma.sync.aligned.m16n8k16.row.col.f32.f16.f16.f32 "
        "{%0,%1,%2,%3}, {%4,%5,%6,%7}, {%8,%9}, {%0,%1,%2,%3};"
        : "+f"(d[0]), "+f"(d[1]), "+f"(d[2]), "+f"(d[3])
        : "r"(a[0]), "r"(a[1]), "r"(a[2]), "r"(a[3]), "r"(b0), "r"(b1));
}
__device__ __forceinline__ void cp16(uint32_t dst, const void* src) {
    asm volatile("cp.async.cg.shared.global [%0], [%1], 16;" :: "r"(dst), "l"(src));
}
#define CP_COMMIT() asm volatile("cp.async.commit_group;" ::: "memory")
#define CP_WAIT1()  asm volatile("cp.async.wait_group 1;" ::: "memory")
#define CP_WAIT0()  asm volatile("cp.async.wait_group 0;" ::: "memory")

__device__ __forceinline__ uint32_t packhf(float e1, float e0) {
    uint32_t r; asm("cvt.rn.f16x2.f32 %0, %1, %2;" : "=r"(r) : "f"(e1), "f"(e0)); return r;
}
__device__ __forceinline__ float ex2f(float x) {
    float y; asm("ex2.approx.ftz.f32 %0, %1;" : "=f"(y) : "f"(x)); return y;
}

// ---------------------------------------------------------------------------
// Fused conversion kernel.
//   blocks [0, 2048):    x [M,K] fp32 -> g_A fp16 (16 elems/thread)
//   blocks [2048, 5120): W [K,N] fp32 -> g_B [N,K] fp16 (32x32 transpose tiles)
// ---------------------------------------------------------------------------
__global__ __launch_bounds__(256) void conv_fused(const float* __restrict__ x,
                                                  const float* __restrict__ W)
{
    if (blockIdx.x < 2048) {
        const int base = (blockIdx.x * 256 + threadIdx.x) * 16;
        float4 v0 = *(const float4*)(x + base);
        float4 v1 = *(const float4*)(x + base + 4);
        float4 v2 = *(const float4*)(x + base + 8);
        float4 v3 = *(const float4*)(x + base + 12);
        __half h[16];
        h[0]  = __float2half(v0.x); h[1]  = __float2half(v0.y);
        h[2]  = __float2half(v0.z); h[3]  = __float2half(v0.w);
        h[4]  = __float2half(v1.x); h[5]  = __float2half(v1.y);
        h[6]  = __float2half(v1.z); h[7]  = __float2half(v1.w);
        h[8]  = __float2half(v2.x); h[9]  = __float2half(v2.y);
        h[10] = __float2half(v2.z); h[11] = __float2half(v2.w);
        h[12] = __float2half(v3.x); h[13] = __float2half(v3.y);
        h[14] = __float2half(v3.z); h[15] = __float2half(v3.w);
        *(float4*)(g_A + base)     = *(float4*)h;
        *(float4*)(g_A + base + 8) = *(float4*)(h + 8);
    } else {
        __shared__ float T[32][33];
        const int blk = blockIdx.x - 2048;
        const int n0 = (blk % 96) * 32;
        const int k0 = (blk / 96) * 32;
        const int tid = threadIdx.x;
        const int tx = tid & 31, ty = tid >> 5;

        #pragma unroll
        for (int i = 0; i < 4; i++)
            T[ty + i * 8][tx] = W[(size_t)(k0 + ty + i * 8) * NTOT + n0 + tx];
        __syncthreads();

        if (tid < 128) {
            const int nl = tid >> 2;
            const int kq = (tid & 3) * 8;
            __half h[8];
            #pragma unroll
            for (int i = 0; i < 8; i++) h[i] = __float2half(T[kq + i][nl]);
            *(float4*)(g_B + (size_t)(n0 + nl) * KTOT + k0 + kq) = *(float4*)h;
        }
    }
}

// ---------------------------------------------------------------------------
// HMMA GEMM (R14 config): C[8192,3072] = A @ B^T. CTA 128x128, warp tile
// 64x32 (2x4 warps, 256 threads), BK=64 (pitch 144B), 3-stage cp.async,
// 2 CTAs/SM. Epilogue: smem-restaged coalesced stores -> Q(xQSCALE)/K/V^T.
// ---------------------------------------------------------------------------
#define GROWB 144
#define GSTG_BYTES (256*GROWB)       // 36864 (A rows 0-127, B rows 128-255)
#define GB_OFF (128*GROWB)           // 18432
#define GSTG 3
#define GEMM_SMEM (GSTG*GSTG_BYTES)  // 110592
#define EPW 5120                     // per-warp epilogue staging region

__device__ __forceinline__ void gemm_load_stage(uint32_t smb, int s, int kc,
                                                int m0, int n0, int tid)
{
    const uint32_t base = smb + s * GSTG_BYTES;
    #pragma unroll
    for (int i = 0; i < 8; i++) {
        const int idx = i * 256 + tid;      // 0..2047
        const int row = idx >> 3, c = idx & 7;
        const __half* src = (row < 128)
            ? g_A + (size_t)(m0 + row) * KTOT + kc + c * 8
            : g_B + (size_t)(n0 + row - 128) * KTOT + kc + c * 8;
        cp16(base + row * GROWB + c * 16, src);
    }
}

__global__ __launch_bounds__(256, 2) void qkv_gemm_hmma(const float* __restrict__ bias)
{
    extern __shared__ __align__(16) char sm[];
    const uint32_t smb = smem_u32(sm);
    const int tid = threadIdx.x, lane = tid & 31, wid = tid >> 5;
    const int m0 = blockIdx.y * 128;
    const int n0 = blockIdx.x * 128;
    const int wm = wid & 1;
    const int wn = wid >> 1;

    float acc[4][4][4];
    #pragma unroll
    for (int i = 0; i < 4; i++)
        #pragma unroll
        for (int j = 0; j < 4; j++)
            #pragma unroll
            for (int r = 0; r < 4; r++) acc[i][j][r] = 0.0f;

    const uint32_t arow_off = (wm * 64 + (lane & 15)) * GROWB;
    const uint32_t brow_off = GB_OFF + (wn * 32 + (lane & 15)) * GROWB;
    const uint32_t lhalf = (lane >> 4) * 16;

    gemm_load_stage(smb, 0, 0,  m0, n0, tid);
    CP_COMMIT();
    gemm_load_stage(smb, 1, 64, m0, n0, tid);
    CP_COMMIT();

    const int NIT = KTOT / 64;   // 16
    for (int it = 0; it < NIT; it++) {
        CP_WAIT1();
        __syncthreads();
        if (it + 2 < NIT)
            gemm_load_stage(smb, (it + 2) % GSTG, (it + 2) * 64, m0, n0, tid);
        CP_COMMIT();

        const uint32_t sb = smb + (it % GSTG) * GSTG_BYTES;
        #pragma unroll
        for (int ks = 0; ks < 4; ks++) {
            const uint32_t koff = ks * 32 + lhalf;
            uint32_t a[4][4], b[2][4];
            #pragma unroll
            for (int mt = 0; mt < 4; mt++)
                ldm_x4(a[mt], sb + arow_off + mt * 16 * GROWB + koff);
            #pragma unroll
            for (int bt = 0; bt < 2; bt++)
                ldm_x4(b[bt], sb + brow_off + bt * 16 * GROWB + koff);
            #pragma unroll
            for (int mt = 0; mt < 4; mt++)
                #pragma unroll
                for (int nt = 0; nt < 4; nt++) {
                    const int bt = nt >> 1, sub = nt & 1;
                    mma16816(acc[mt][nt], a[mt], b[bt][sub], b[bt][sub + 2]);
                }
        }
    }

    // ---- Epilogue: smem restage per warp, then coalesced global stores ----
    __syncthreads();

    const int seg   = (n0 + wn * 32) >> 6;
    const int hh    = seg / 3;
    const int which = seg % 3;
    const int dh0   = (wn & 1) * 32;
    const int bi    = m0 >> 11;
    const int si0   = (m0 & 2047) + wm * 64;
    const int bh    = bi * HH + hh;
    char* ep = sm + wid * EPW;
    const float scl = (which == 0) ? QSCALE : 1.0f;

    if (which != 2) {
        #pragma unroll
        for (int nt = 0; nt < 4; nt++) {
            const int c = (nt >> 1) * 16 + (nt & 1) * 8 + 2 * (lane & 3);
            const float2 bb = *(const float2*)(bias + n0 + wn * 32 + c);
            #pragma unroll
            for (int mt = 0; mt < 4; mt++)
                #pragma unroll
                for (int rr = 0; rr < 2; rr++) {
                    const int r = mt * 16 + (lane >> 2) + rr * 8;
                    const float vx = (acc[mt][nt][rr * 2 + 0] + bb.x) * scl;
                    const float vy = (acc[mt][nt][rr * 2 + 1] + bb.y) * scl;
                    *(uint32_t*)(ep + r * 72 + c * 2) = packhf(vy, vx);
                }
        }
        __syncwarp();
        __half* dstb = ((which == 0) ? g_Qh : g_Kh)
                     + ((size_t)bh * SS + si0) * DHH + dh0;
        #pragma unroll
        for (int p = 0; p < 16; p++) {
            const int slot = p * 32 + lane;
            const int r = slot >> 3, ch = slot & 7;
            float2 v = *(float2*)(ep + r * 72 + ch * 8);
            *(float2*)(dstb + (size_t)r * DHH + ch * 4) = v;
        }
    } else {
        #pragma unroll
        for (int nt = 0; nt < 4; nt++) {
            const int c = (nt >> 1) * 16 + (nt & 1) * 8 + 2 * (lane & 3);
            const float2 bb = *(const float2*)(bias + n0 + wn * 32 + c);
            #pragma unroll
            for (int mt = 0; mt < 4; mt++)
                #pragma unroll
                for (int rr = 0; rr < 2; rr++) {
                    const int r = mt * 16 + (lane >> 2) + rr * 8;
                    *(__half*)(ep + c * 136 + r * 2)       = __float2half(acc[mt][nt][rr*2+0] + bb.x);
                    *(__half*)(ep + (c + 1) * 136 + r * 2) = __float2half(acc[mt][nt][rr*2+1] + bb.y);
                }
        }
        __syncwarp();
        __half* dstb = g_Vh + ((size_t)bh * DHH + dh0) * SS + si0;
        #pragma unroll
        for (int p = 0; p < 16; p++) {
            const int slot = p * 32 + lane;
            const int d = slot >> 4, ch = slot & 15;
            float2 v = *(float2*)(ep + d * 136 + ch * 8);
            *(float2*)(dstb + (size_t)d * SS + ch * 4) = v;
        }
    }
}

// ---------------------------------------------------------------------------
// HMMA causal flash attention, fp16, exp2-space softmax (ex2.approx).
// CTA: 64 q rows, 4 warps x 16 rows. Q in dedicated smem -> 4 CTAs/SM.
// Q staging via cp.async, overlapped with K/V tile-0 preload (single group).
// Balanced dual-q-tile CTAs: grid (16, 64); CTA p handles q-tiles {p, 31-p}.
// ---------------------------------------------------------------------------
#define APITCH 144
#define AST 18432          // stage bytes: Kh@0, Vh@9216 (64 rows x 144B)
#define AQ_OFF (2*AST)     // Q region: 36864..46080
#define ATT_SMEM (2*AST + 9216)  // 46080

__global__ __launch_bounds__(128, 4) void attn_hmma(float* __restrict__ out)
{
    extern __shared__ __align__(16) char sm[];
    const uint32_t smb = smem_u32(sm);
    const int tid = threadIdx.x, lane = tid & 31, w = tid >> 5;
    const int bh = blockIdx.y;
    const int tg = lane & 3, g = lane >> 2;
    const int b = bh >> 4, h = bh & 15;

    const __half* khb = g_Kh + (size_t)bh * SS * DHH;
    const __half* vhb = g_Vh + (size_t)bh * DHH * SS;

    const uint32_t qfrag = smb + AQ_OFF + (w * 16 + (lane & 15)) * APITCH
                         + (lane >> 4) * 16;

    #pragma unroll 1
    for (int segi = 0; segi < 2; segi++) {
        const int qt = segi ? (31 - (int)blockIdx.x) : (int)blockIdx.x;
        const int q0 = qt * 64;

        __syncthreads();   // prior segment's smem (Q region + stage 0/1) reads done

        // --- Q staging (cp.async) + K/V tile-0 preload, one commit group ---
        {
            const __half* qhg = g_Qh + ((size_t)bh * SS + q0) * DHH;
            #pragma unroll
            for (int i = 0; i < 4; i++) {
                const int idx = i * 128 + tid;
                const int row = idx >> 3, c = idx & 7;
                cp16(smb + AQ_OFF + row * APITCH + c * 16, qhg + row * 64 + c * 8);
            }
            #pragma unroll
            for (int i = 0; i < 4; i++) {
                const int idx = i * 128 + tid;
                const int row = idx >> 3, c = idx & 7;
                cp16(smb + row * APITCH + c * 16,        khb + row * 64 + c * 8);
                cp16(smb + 9216 + row * APITCH + c * 16, vhb + (size_t)row * SS + c * 8);
            }
        }
        CP_COMMIT();

        float o[8][4];
        #pragma unroll
        for (int nt = 0; nt < 8; nt++)
            #pragma unroll
            for (int e = 0; e < 4; e++) o[nt][e] = 0.0f;
        float mrow[2] = {-1e30f, -1e30f};
        float lrow[2] = {0.f, 0.f};

        const int nkt = qt + 1;

        #pragma unroll 1
        for (int jt = 0; jt < nkt; jt++) {
            CP_WAIT0();
            __syncthreads();   // K/V tile + Q (first iter) visible to all warps
            if (jt + 1 < nkt) {
                const uint32_t base = smb + ((jt + 1) & 1) * AST;
                const int j1 = (jt + 1) * 64;
                #pragma unroll
                for (int i = 0; i < 4; i++) {
                    const int idx = i * 128 + tid;
                    const int row = idx >> 3, c = idx & 7;
                    cp16(base + row * APITCH + c * 16,        khb + (size_t)(j1 + row) * 64 + c * 8);
                    cp16(base + 9216 + row * APITCH + c * 16, vhb + (size_t)row * SS + j1 + c * 8);
                }
            }
            CP_COMMIT();

            const uint32_t kb = smb + (jt & 1) * AST;
            const int j0 = jt * 64;

            // ---- S = Q K^T (log2 units via Q pre-scale); Q frags from smem ----
            float s2[8][4];
            #pragma unroll
            for (int nt = 0; nt < 8; nt++)
                #pragma unroll
                for (int e = 0; e < 4; e++) s2[nt][e] = 0.0f;

            #pragma unroll
            for (int kc = 0; kc < 4; kc++) {
                uint32_t qf[4];
                ldm_x4(qf, qfrag + kc * 32);
                uint32_t bf[4][4];
                #pragma unroll
                for (int bt = 0; bt < 4; bt++)
                    ldm_x4(bf[bt], kb + (bt * 16 + (lane & 15)) * APITCH
                                 + (kc * 2 + (lane >> 4)) * 16);
                #pragma unroll
                for (int nt = 0; nt < 8; nt++)
                    mma16816(s2[nt], qf, bf[nt >> 1][nt & 1], bf[nt >> 1][(nt & 1) + 2]);
            }

            // ---- mask + online softmax (exp2 space) ----
            const bool need_mask = (j0 + 63 > q0 + w * 16);
            #pragma unroll
            for (int rs = 0; rs < 2; rs++) {
                const int row = q0 + w * 16 + g + rs * 8;
                if (need_mask) {
                    #pragma unroll
                    for (int nt = 0; nt < 8; nt++)
                        #pragma unroll
                        for (int e = 0; e < 2; e++) {
                            const int key = j0 + nt * 8 + tg * 2 + e;
                            if (key > row) s2[nt][rs * 2 + e] = -1e30f;
                        }
                }
                float mx = -1e30f;
                #pragma unroll
                for (int nt = 0; nt < 8; nt++)
                    mx = fmaxf(mx, fmaxf(s2[nt][rs * 2], s2[nt][rs * 2 + 1]));
                mx = fmaxf(mx, __shfl_xor_sync(0xffffffffu, mx, 1));
                mx = fmaxf(mx, __shfl_xor_sync(0xffffffffu, mx, 2));
                const float mn = fmaxf(mrow[rs], mx);
                const float sc = ex2f(mrow[rs] - mn);
                mrow[rs] = mn;
                float ps = 0.0f;
                #pragma unroll
                for (int nt = 0; nt < 8; nt++) {
                    float p0 = ex2f(s2[nt][rs * 2]     - mn);
                    float p1 = ex2f(s2[nt][rs * 2 + 1] - mn);
                    s2[nt][rs * 2] = p0; s2[nt][rs * 2 + 1] = p1;
                    ps += p0 + p1;
                    o[nt][rs * 2] *= sc; o[nt][rs * 2 + 1] *= sc;
                }
                lrow[rs] = lrow[rs] * sc + ps;
            }

            // ---- O += P V ----
            #pragma unroll
            for (int kc = 0; kc < 4; kc++) {
                uint32_t bf[4][4];
                #pragma unroll
                for (int bt = 0; bt < 4; bt++)
                    ldm_x4(bf[bt], kb + 9216 + (bt * 16 + (lane & 15)) * APITCH
                                 + (kc * 2 + (lane >> 4)) * 16);
                uint32_t a[4];
                a[0] = packhf(s2[2*kc][1],   s2[2*kc][0]);
                a[1] = packhf(s2[2*kc][3],   s2[2*kc][2]);
                a[2] = packhf(s2[2*kc+1][1], s2[2*kc+1][0]);
                a[3] = packhf(s2[2*kc+1][3], s2[2*kc+1][2]);
                #pragma unroll
                for (int nt = 0; nt < 8; nt++)
                    mma16816(o[nt], a, bf[nt >> 1][nt & 1], bf[nt >> 1][(nt & 1) + 2]);
            }
        }

        // ---- finalize: normalize, write out[b, s, h*64+dh] ----
        float l0 = lrow[0];
        l0 += __shfl_xor_sync(0xffffffffu, l0, 1);
        l0 += __shfl_xor_sync(0xffffffffu, l0, 2);
        float l1 = lrow[1];
        l1 += __shfl_xor_sync(0xffffffffu, l1, 1);
        l1 += __shfl_xor_sync(0xffffffffu, l1, 2);
        const float i0 = 1.0f / l0, i1 = 1.0f / l1;
        const int row = q0 + w * 16 + g;
        #pragma unroll
        for (int nt = 0; nt < 8; nt++) {
            const int col = h * 64 + nt * 8 + tg * 2;
            float2 v0 = make_float2(o[nt][0] * i0, o[nt][1] * i0);
            *(float2*)(out + ((size_t)(b * SS + row)) * DD + col) = v0;
            float2 v1 = make_float2(o[nt][2] * i1, o[nt][3] * i1);
            *(float2*)(out + ((size_t)(b * SS + row + 8)) * DD + col) = v1;
        }
    }
}

// ---------------------------------------------------------------------------
extern "C" void kernel_launch(void* const* d_in, const int* in_sizes, int n_in,
                              void* d_out, int out_size)
{
    const float* x    = (const float*)d_in[0];   // [B,S,D]
    const float* W    = (const float*)d_in[1];   // [D,3D]
    const float* bias = (const float*)d_in[2];   // [3D]
    float* out        = (float*)d_out;           // [B,S,D]

    cudaFuncSetAttribute(qkv_gemm_hmma, cudaFuncAttributeMaxDynamicSharedMemorySize, GEMM_SMEM);
    cudaFuncSetAttribute(attn_hmma,     cudaFuncAttributeMaxDynamicSharedMemorySize, ATT_SMEM);

    conv_fused<<<2048 + 3072, 256>>>(x, W);

    dim3 gemm_grid(NTOT / 128, MTOT / 128);   // (24, 64)
    qkv_gemm_hmma<<<gemm_grid, 256, GEMM_SMEM>>>(bias);

    dim3 attn_grid(16, BB * HH);              // (16, 64), dual q-tiles per CTA
    attn_hmma<<<attn_grid, 128, ATT_SMEM>>>(out);
}

// round 17
// speedup vs baseline: 1.0356x; 1.0356x over previous
#include <cuda_runtime.h>
#include <cuda_fp16.h>
#include <cstdint>

// Problem constants
#define BB 4
#define SS 2048
#define DD 1024
#define HH 16
#define DHH 64
#define MTOT (BB*SS)     // 8192
#define NTOT (3*DD)      // 3072
#define KTOT (DD)        // 1024

#define QKVN ((size_t)BB*HH*SS*DHH)

// Q pre-scale: 1/sqrt(64) * log2(e)  (softmax done in exp2 space)
#define QSCALE 0.1803368801111204f

// Scratch: fp16 single-precision-pass operands
__device__ __align__(16) __half g_A[(size_t)MTOT*KTOT];   // x   [M, K] K-major
__device__ __align__(16) __half g_B[(size_t)NTOT*KTOT];   // W^T [N, K] K-major
__device__ __align__(16) __half g_Qh[QKVN];               // [B,H,S,64] (pre-scaled)
__device__ __align__(16) __half g_Kh[QKVN];               // [B,H,S,64]
__device__ __align__(16) __half g_Vh[QKVN];               // [B,H,64,S] (transposed)

// ---------------------------------------------------------------------------
// Helpers (sm_103 baseline-safe: ldmatrix / mma.sync / cp.async only)
// ---------------------------------------------------------------------------
__device__ __forceinline__ uint32_t smem_u32(const void* p) {
    uint32_t a;
    asm("{ .reg .u64 t; cvta.to.shared.u64 t, %1; cvt.u32.u64 %0, t; }" : "=r"(a) : "l"(p));
    return a;
}
__device__ __forceinline__ void ldm_x4(uint32_t* r, uint32_t addr) {
    asm volatile("ldmatrix.sync.aligned.m8n8.x4.shared.b16 {%0,%1,%2,%3}, [%4];"
        : "=r"(r[0]), "=r"(r[1]), "=r"(r[2]), "=r"(r[3]) : "r"(addr));
}
__device__ __forceinline__ void mma16816(float* d, const uint32_t* a, uint32_t b0, uint32_t b1) {
    asm volatile("mma.sync.aligned.m16n8k16.row.col.f32.f16.f16.f32 "
        "{%0,%1,%2,%3}, {%4,%5,%6,%7}, {%8,%9}, {%0,%1,%2,%3};"
        : "+f"(d[0]), "+f"(d[1]), "+f"(d[2]), "+f"(d[3])
        : "r"(a[0]), "r"(a[1]), "r"(a[2]), "r"(a[3]), "r"(b0), "r"(b1));
}
__device__ __forceinline__ void cp16(uint32_t dst, const void* src) {
    asm volatile("cp.async.cg.shared.global [%0], [%1], 16;" :: "r"(dst), "l"(src));
}
#define CP_COMMIT() asm volatile("cp.async.commit_group;" ::: "memory")
#define CP_WAIT1()  asm volatile("cp.async.wait_group 1;" ::: "memory")
#define CP_WAIT0()  asm volatile("cp.async.wait_group 0;" ::: "memory")

__device__ __forceinline__ uint32_t packhf(float e1, float e0) {
    uint32_t r; asm("cvt.rn.f16x2.f32 %0, %1, %2;" : "=r"(r) : "f"(e1), "f"(e0)); return r;
}
__device__ __forceinline__ float ex2f(float x) {
    float y; asm("ex2.approx.ftz.f32 %0, %1;" : "=f"(y) : "f"(x)); return y;
}

// ---------------------------------------------------------------------------
// Fused conversion kernel.
//   blocks [0, 2048):    x [M,K] fp32 -> g_A fp16 (16 elems/thread)
//   blocks [2048, 5120): W [K,N] fp32 -> g_B [N,K] fp16 (32x32 transpose tiles)
// ---------------------------------------------------------------------------
__global__ __launch_bounds__(256) void conv_fused(const float* __restrict__ x,
                                                  const float* __restrict__ W)
{
    if (blockIdx.x < 2048) {
        const int base = (blockIdx.x * 256 + threadIdx.x) * 16;
        float4 v0 = *(const float4*)(x + base);
        float4 v1 = *(const float4*)(x + base + 4);
        float4 v2 = *(const float4*)(x + base + 8);
        float4 v3 = *(const float4*)(x + base + 12);
        __half h[16];
        h[0]  = __float2half(v0.x); h[1]  = __float2half(v0.y);
        h[2]  = __float2half(v0.z); h[3]  = __float2half(v0.w);
        h[4]  = __float2half(v1.x); h[5]  = __float2half(v1.y);
        h[6]  = __float2half(v1.z); h[7]  = __float2half(v1.w);
        h[8]  = __float2half(v2.x); h[9]  = __float2half(v2.y);
        h[10] = __float2half(v2.z); h[11] = __float2half(v2.w);
        h[12] = __float2half(v3.x); h[13] = __float2half(v3.y);
        h[14] = __float2half(v3.z); h[15] = __float2half(v3.w);
        *(float4*)(g_A + base)     = *(float4*)h;
        *(float4*)(g_A + base + 8) = *(float4*)(h + 8);
    } else {
        __shared__ float T[32][33];
        const int blk = blockIdx.x - 2048;
        const int n0 = (blk % 96) * 32;
        const int k0 = (blk / 96) * 32;
        const int tid = threadIdx.x;
        const int tx = tid & 31, ty = tid >> 5;

        #pragma unroll
        for (int i = 0; i < 4; i++)
            T[ty + i * 8][tx] = W[(size_t)(k0 + ty + i * 8) * NTOT + n0 + tx];
        __syncthreads();

        if (tid < 128) {
            const int nl = tid >> 2;
            const int kq = (tid & 3) * 8;
            __half h[8];
            #pragma unroll
            for (int i = 0; i < 8; i++) h[i] = __float2half(T[kq + i][nl]);
            *(float4*)(g_B + (size_t)(n0 + nl) * KTOT + k0 + kq) = *(float4*)h;
        }
    }
}

// ---------------------------------------------------------------------------
// HMMA GEMM (R14 config): C[8192,3072] = A @ B^T. CTA 128x128, warp tile
// 64x32 (2x4 warps, 256 threads), BK=64 (pitch 144B), 3-stage cp.async,
// 2 CTAs/SM. Epilogue: smem-restaged coalesced stores -> Q(xQSCALE)/K/V^T.
// ---------------------------------------------------------------------------
#define GROWB 144
#define GSTG_BYTES (256*GROWB)       // 36864 (A rows 0-127, B rows 128-255)
#define GB_OFF (128*GROWB)           // 18432
#define GSTG 3
#define GEMM_SMEM (GSTG*GSTG_BYTES)  // 110592
#define EPW 5120                     // per-warp epilogue staging region

__device__ __forceinline__ void gemm_load_stage(uint32_t smb, int s, int kc,
                                                int m0, int n0, int tid)
{
    const uint32_t base = smb + s * GSTG_BYTES;
    #pragma unroll
    for (int i = 0; i < 8; i++) {
        const int idx = i * 256 + tid;      // 0..2047
        const int row = idx >> 3, c = idx & 7;
        const __half* src = (row < 128)
            ? g_A + (size_t)(m0 + row) * KTOT + kc + c * 8
            : g_B + (size_t)(n0 + row - 128) * KTOT + kc + c * 8;
        cp16(base + row * GROWB + c * 16, src);
    }
}

__global__ __launch_bounds__(256, 2) void qkv_gemm_hmma(const float* __restrict__ bias)
{
    extern __shared__ __align__(16) char sm[];
    const uint32_t smb = smem_u32(sm);
    const int tid = threadIdx.x, lane = tid & 31, wid = tid >> 5;
    const int m0 = blockIdx.y * 128;
    const int n0 = blockIdx.x * 128;
    const int wm = wid & 1;
    const int wn = wid >> 1;

    float acc[4][4][4];
    #pragma unroll
    for (int i = 0; i < 4; i++)
        #pragma unroll
        for (int j = 0; j < 4; j++)
            #pragma unroll
            for (int r = 0; r < 4; r++) acc[i][j][r] = 0.0f;

    const uint32_t arow_off = (wm * 64 + (lane & 15)) * GROWB;
    const uint32_t brow_off = GB_OFF + (wn * 32 + (lane & 15)) * GROWB;
    const uint32_t lhalf = (lane >> 4) * 16;

    gemm_load_stage(smb, 0, 0,  m0, n0, tid);
    CP_COMMIT();
    gemm_load_stage(smb, 1, 64, m0, n0, tid);
    CP_COMMIT();

    const int NIT = KTOT / 64;   // 16
    for (int it = 0; it < NIT; it++) {
        CP_WAIT1();
        __syncthreads();
        if (it + 2 < NIT)
            gemm_load_stage(smb, (it + 2) % GSTG, (it + 2) * 64, m0, n0, tid);
        CP_COMMIT();

        const uint32_t sb = smb + (it % GSTG) * GSTG_BYTES;
        #pragma unroll
        for (int ks = 0; ks < 4; ks++) {
            const uint32_t koff = ks * 32 + lhalf;
            uint32_t a[4][4], b[2][4];
            #pragma unroll
            for (int mt = 0; mt < 4; mt++)
                ldm_x4(a[mt], sb + arow_off + mt * 16 * GROWB + koff);
            #pragma unroll
            for (int bt = 0; bt < 2; bt++)
                ldm_x4(b[bt], sb + brow_off + bt * 16 * GROWB + koff);
            #pragma unroll
            for (int mt = 0; mt < 4; mt++)
                #pragma unroll
                for (int nt = 0; nt < 4; nt++) {
                    const int bt = nt >> 1, sub = nt & 1;
                    mma16816(acc[mt][nt], a[mt], b[bt][sub], b[bt][sub + 2]);
                }
        }
    }

    // ---- Epilogue: smem restage per warp, then coalesced global stores ----
    __syncthreads();

    const int seg   = (n0 + wn * 32) >> 6;
    const int hh    = seg / 3;
    const int which = seg % 3;
    const int dh0   = (wn & 1) * 32;
    const int bi    = m0 >> 11;
    const int si0   = (m0 & 2047) + wm * 64;
    const int bh    = bi * HH + hh;
    char* ep = sm + wid * EPW;
    const float scl = (which == 0) ? QSCALE : 1.0f;

    if (which != 2) {
        #pragma unroll
        for (int nt = 0; nt < 4; nt++) {
            const int c = (nt >> 1) * 16 + (nt & 1) * 8 + 2 * (lane & 3);
            const float2 bb = *(const float2*)(bias + n0 + wn * 32 + c);
            #pragma unroll
            for (int mt = 0; mt < 4; mt++)
                #pragma unroll
                for (int rr = 0; rr < 2; rr++) {
                    const int r = mt * 16 + (lane >> 2) + rr * 8;
                    const float vx = (acc[mt][nt][rr * 2 + 0] + bb.x) * scl;
                    const float vy = (acc[mt][nt][rr * 2 + 1] + bb.y) * scl;
                    *(uint32_t*)(ep + r * 72 + c * 2) = packhf(vy, vx);
                }
        }
        __syncwarp();
        __half* dstb = ((which == 0) ? g_Qh : g_Kh)
                     + ((size_t)bh * SS + si0) * DHH + dh0;
        #pragma unroll
        for (int p = 0; p < 16; p++) {
            const int slot = p * 32 + lane;
            const int r = slot >> 3, ch = slot & 7;
            float2 v = *(float2*)(ep + r * 72 + ch * 8);
            *(float2*)(dstb + (size_t)r * DHH + ch * 4) = v;
        }
    } else {
        #pragma unroll
        for (int nt = 0; nt < 4; nt++) {
            const int c = (nt >> 1) * 16 + (nt & 1) * 8 + 2 * (lane & 3);
            const float2 bb = *(const float2*)(bias + n0 + wn * 32 + c);
            #pragma unroll
            for (int mt = 0; mt < 4; mt++)
                #pragma unroll
                for (int rr = 0; rr < 2; rr++) {
                    const int r = mt * 16 + (lane >> 2) + rr * 8;
                    *(__half*)(ep + c * 136 + r * 2)       = __float2half(acc[mt][nt][rr*2+0] + bb.x);
                    *(__half*)(ep + (c + 1) * 136 + r * 2) = __float2half(acc[mt][nt][rr*2+1] + bb.y);
                }
        }
        __syncwarp();
        __half* dstb = g_Vh + ((size_t)bh * DHH + dh0) * SS + si0;
        #pragma unroll
        for (int p = 0; p < 16; p++) {
            const int slot = p * 32 + lane;
            const int d = slot >> 4, ch = slot & 15;
            float2 v = *(float2*)(ep + d * 136 + ch * 8);
            *(float2*)(dstb + (size_t)d * SS + ch * 4) = v;
        }
    }
}

// ---------------------------------------------------------------------------
// HMMA causal flash attention, fp16, exp2-space softmax (ex2.approx).
// CTA: 64 q rows, 4 warps x 16 rows. Q in dedicated smem -> 4 CTAs/SM.
// LPT scheduling: grid (bh=64, qtr=32), qt = 31 - blockIdx.y. Linear block
// issue order launches all heaviest (qt=31, 33-tile) CTAs first; hardware
// backfills lighter CTAs as slots free -> makespan near the 57.1-tile ideal.
// ---------------------------------------------------------------------------
#define APITCH 144
#define AST 18432          // stage bytes: Kh@0, Vh@9216 (64 rows x 144B)
#define AQ_OFF (2*AST)     // Q region: 36864..46080
#define ATT_SMEM (2*AST + 9216)  // 46080

__global__ __launch_bounds__(128, 4) void attn_hmma(float* __restrict__ out)
{
    extern __shared__ __align__(16) char sm[];
    const uint32_t smb = smem_u32(sm);
    const int tid = threadIdx.x, lane = tid & 31, w = tid >> 5;
    const int bh = blockIdx.x;                 // 0..63
    const int qt = 31 - (int)blockIdx.y;       // heavy CTAs first in issue order
    const int q0 = qt * 64;
    const int tg = lane & 3, g = lane >> 2;
    const int b = bh >> 4, h = bh & 15;

    const __half* khb = g_Kh + (size_t)bh * SS * DHH;
    const __half* vhb = g_Vh + (size_t)bh * DHH * SS;

    const uint32_t qfrag = smb + AQ_OFF + (w * 16 + (lane & 15)) * APITCH
                         + (lane >> 4) * 16;

    // --- stage Q tile (64 rows) into dedicated smem region ---
    {
        const __half* qhg = g_Qh + ((size_t)bh * SS + q0) * DHH;
        #pragma unroll
        for (int i = 0; i < 4; i++) {
            const int idx = i * 128 + tid;
            const int row = idx >> 3, c = idx & 7;
            *(float4*)(sm + AQ_OFF + row * APITCH + c * 16)
                = *(const float4*)(qhg + row * 64 + c * 8);
        }
    }

    float o[8][4];
    #pragma unroll
    for (int nt = 0; nt < 8; nt++)
        #pragma unroll
        for (int e = 0; e < 4; e++) o[nt][e] = 0.0f;
    float mrow[2] = {-1e30f, -1e30f};
    float lrow[2] = {0.f, 0.f};

    const int nkt = qt + 1;

    // preload tile 0
    #pragma unroll
    for (int i = 0; i < 4; i++) {
        const int idx = i * 128 + tid;
        const int row = idx >> 3, c = idx & 7;
        cp16(smb + row * APITCH + c * 16,        khb + row * 64 + c * 8);
        cp16(smb + 9216 + row * APITCH + c * 16, vhb + (size_t)row * SS + c * 8);
    }
    CP_COMMIT();

    #pragma unroll 1
    for (int jt = 0; jt < nkt; jt++) {
        CP_WAIT0();
        __syncthreads();   // K/V tile ready + Q staged (first iter)
        if (jt + 1 < nkt) {
            const uint32_t base = smb + ((jt + 1) & 1) * AST;
            const int j1 = (jt + 1) * 64;
            #pragma unroll
            for (int i = 0; i < 4; i++) {
                const int idx = i * 128 + tid;
                const int row = idx >> 3, c = idx & 7;
                cp16(base + row * APITCH + c * 16,        khb + (size_t)(j1 + row) * 64 + c * 8);
                cp16(base + 9216 + row * APITCH + c * 16, vhb + (size_t)row * SS + j1 + c * 8);
            }
        }
        CP_COMMIT();

        const uint32_t kb = smb + (jt & 1) * AST;
        const int j0 = jt * 64;

        // ---- S = Q K^T (log2 units via Q pre-scale); Q frags from smem ----
        float s2[8][4];
        #pragma unroll
        for (int nt = 0; nt < 8; nt++)
            #pragma unroll
            for (int e = 0; e < 4; e++) s2[nt][e] = 0.0f;

        #pragma unroll
        for (int kc = 0; kc < 4; kc++) {
            uint32_t qf[4];
            ldm_x4(qf, qfrag + kc * 32);
            uint32_t bf[4][4];
            #pragma unroll
            for (int bt = 0; bt < 4; bt++)
                ldm_x4(bf[bt], kb + (bt * 16 + (lane & 15)) * APITCH
                             + (kc * 2 + (lane >> 4)) * 16);
            #pragma unroll
            for (int nt = 0; nt < 8; nt++)
                mma16816(s2[nt], qf, bf[nt >> 1][nt & 1], bf[nt >> 1][(nt & 1) + 2]);
        }

        // ---- mask + online softmax (exp2 space) ----
        const bool need_mask = (j0 + 63 > q0 + w * 16);
        #pragma unroll
        for (int rs = 0; rs < 2; rs++) {
            const int row = q0 + w * 16 + g + rs * 8;
            if (need_mask) {
                #pragma unroll
                for (int nt = 0; nt < 8; nt++)
                    #pragma unroll
                    for (int e = 0; e < 2; e++) {
                        const int key = j0 + nt * 8 + tg * 2 + e;
                        if (key > row) s2[nt][rs * 2 + e] = -1e30f;
                    }
            }
            float mx = -1e30f;
            #pragma unroll
            for (int nt = 0; nt < 8; nt++)
                mx = fmaxf(mx, fmaxf(s2[nt][rs * 2], s2[nt][rs * 2 + 1]));
            mx = fmaxf(mx, __shfl_xor_sync(0xffffffffu, mx, 1));
            mx = fmaxf(mx, __shfl_xor_sync(0xffffffffu, mx, 2));
            const float mn = fmaxf(mrow[rs], mx);
            const float sc = ex2f(mrow[rs] - mn);
            mrow[rs] = mn;
            float ps = 0.0f;
            #pragma unroll
            for (int nt = 0; nt < 8; nt++) {
                float p0 = ex2f(s2[nt][rs * 2]     - mn);
                float p1 = ex2f(s2[nt][rs * 2 + 1] - mn);
                s2[nt][rs * 2] = p0; s2[nt][rs * 2 + 1] = p1;
                ps += p0 + p1;
                o[nt][rs * 2] *= sc; o[nt][rs * 2 + 1] *= sc;
            }
            lrow[rs] = lrow[rs] * sc + ps;
        }

        // ---- O += P V ----
        #pragma unroll
        for (int kc = 0; kc < 4; kc++) {
            uint32_t bf[4][4];
            #pragma unroll
            for (int bt = 0; bt < 4; bt++)
                ldm_x4(bf[bt], kb + 9216 + (bt * 16 + (lane & 15)) * APITCH
                             + (kc * 2 + (lane >> 4)) * 16);
            uint32_t a[4];
            a[0] = packhf(s2[2*kc][1],   s2[2*kc][0]);
            a[1] = packhf(s2[2*kc][3],   s2[2*kc][2]);
            a[2] = packhf(s2[2*kc+1][1], s2[2*kc+1][0]);
            a[3] = packhf(s2[2*kc+1][3], s2[2*kc+1][2]);
            #pragma unroll
            for (int nt = 0; nt < 8; nt++)
                mma16816(o[nt], a, bf[nt >> 1][nt & 1], bf[nt >> 1][(nt & 1) + 2]);
        }
    }

    // ---- finalize: normalize, write out[b, s, h*64+dh] ----
    float l0 = lrow[0];
    l0 += __shfl_xor_sync(0xffffffffu, l0, 1);
    l0 += __shfl_xor_sync(0xffffffffu, l0, 2);
    float l1 = lrow[1];
    l1 += __shfl_xor_sync(0xffffffffu, l1, 1);
    l1 += __shfl_xor_sync(0xffffffffu, l1, 2);
    const float i0 = 1.0f / l0, i1 = 1.0f / l1;
    const int row = q0 + w * 16 + g;
    #pragma unroll
    for (int nt = 0; nt < 8; nt++) {
        const int col = h * 64 + nt * 8 + tg * 2;
        float2 v0 = make_float2(o[nt][0] * i0, o[nt][1] * i0);
        *(float2*)(out + ((size_t)(b * SS + row)) * DD + col) = v0;
        float2 v1 = make_float2(o[nt][2] * i1, o[nt][3] * i1);
        *(float2*)(out + ((size_t)(b * SS + row + 8)) * DD + col) = v1;
    }
}

// ---------------------------------------------------------------------------
extern "C" void kernel_launch(void* const* d_in, const int* in_sizes, int n_in,
                              void* d_out, int out_size)
{
    const float* x    = (const float*)d_in[0];   // [B,S,D]
    const float* W    = (const float*)d_in[1];   // [D,3D]
    const float* bias = (const float*)d_in[2];   // [3D]
    float* out        = (float*)d_out;           // [B,S,D]

    cudaFuncSetAttribute(qkv_gemm_hmma, cudaFuncAttributeMaxDynamicSharedMemorySize, GEMM_SMEM);
    cudaFuncSetAttribute(attn_hmma,     cudaFuncAttributeMaxDynamicSharedMemorySize, ATT_SMEM);

    conv_fused<<<2048 + 3072, 256>>>(x, W);

    dim3 gemm_grid(NTOT / 128, MTOT / 128);   // (24, 64)
    qkv_gemm_hmma<<<gemm_grid, 256, GEMM_SMEM>>>(bias);

    dim3 attn_grid(BB * HH, 32);              // (64, 32): one q-tile per CTA, LPT order
    attn_hmma<<<attn_grid, 128, ATT_SMEM>>>(out);
}